// round 14
// baseline (speedup 1.0000x reference)
#include <cuda_runtime.h>
#include <cuda_bf16.h>
#include <cstdint>

// ---------------------------------------------------------------------------
// LinearAttention via polynomial flash attention.
//   phi(q).phi(k) = 1 + s + s^2/2,  s = q.k/4   (Taylor feature identity)
// so causal linear attention == causal polynomial attention:
//   y_t = sum_{s<=t} sc(t,s) v_s / sum_{s<=t} sc(t,s)
//
//   S:  split hs/W1/Wo to K-concat split-bf16 (K=3072)
//   G1: qkv = hs2 @ W1^T   (mma.sync bf16, 512-thr CTA, 4 warps/SMSP)
//   FA: per (tb, h): flash loop over s-blocks: QK^T HMMA (split, K=48),
//       polynomial+mask+fp32 rowsum, score@V HMMA (3 passes, K=128 each),
//       divide, write split-bf16 y2
//   G2: out = y2 @ Wo2^T
// ---------------------------------------------------------------------------

#define LSEQ   1024
#define NH     16
#define EPSV   1e-12f
#define KSPLIT 3072
#define NSTAGE 48
#define ROWB   144

// flash smem layout
#define APITCH 112                       // 48 bf16 cols + pad
#define SPITCH 272                       // 128 bf16 cols + pad
#define AQ_OFF 0
#define BK_OFF 14336
#define SH_OFF 28672
#define SL_OFF 63488
#define VH_OFF 98304
#define VL_OFF 115712
#define DEN_OFF 133120
#define FA_SMEM 135168

// Scratch (static device globals; no allocation allowed)
__device__ __align__(16) float g_qkv[LSEQ * 1536];
__device__ __align__(16) __nv_bfloat16 g_hs2[LSEQ * KSPLIT];
__device__ __align__(16) __nv_bfloat16 g_w1 [1536 * KSPLIT];
__device__ __align__(16) __nv_bfloat16 g_y2 [LSEQ * KSPLIT];
__device__ __align__(16) __nv_bfloat16 g_wo2[1024 * KSPLIT];

// ---------------- PTX helpers -----------------------------------------------
__device__ __forceinline__ uint32_t smem_u32(const void* p) {
    uint32_t a;
    asm("{ .reg .u64 t; cvta.to.shared.u64 t, %1; cvt.u32.u64 %0, t; }"
        : "=r"(a) : "l"(p));
    return a;
}
__device__ __forceinline__ void cp16(uint32_t saddr, const void* g) {
    asm volatile("cp.async.cg.shared.global [%0], [%1], 16;"
                 :: "r"(saddr), "l"(g) : "memory");
}
__device__ __forceinline__ void ldsm_x4(uint32_t& r0, uint32_t& r1,
                                        uint32_t& r2, uint32_t& r3,
                                        uint32_t addr) {
    asm volatile("ldmatrix.sync.aligned.m8n8.x4.shared.b16 {%0,%1,%2,%3}, [%4];"
                 : "=r"(r0), "=r"(r1), "=r"(r2), "=r"(r3) : "r"(addr));
}
__device__ __forceinline__ void mma16816(float* c, const uint32_t* a,
                                         const uint32_t* b) {
    asm volatile("mma.sync.aligned.m16n8k16.row.col.f32.bf16.bf16.f32 "
                 "{%0,%1,%2,%3}, {%4,%5,%6,%7}, {%8,%9}, {%0,%1,%2,%3};"
                 : "+f"(c[0]), "+f"(c[1]), "+f"(c[2]), "+f"(c[3])
                 : "r"(a[0]), "r"(a[1]), "r"(a[2]), "r"(a[3]),
                   "r"(b[0]), "r"(b[1]));
}

// ---------------- fused split kernel ----------------------------------------
__device__ __forceinline__ void split4(float4 x, __nv_bfloat162& h01,
                                       __nv_bfloat162& h23, __nv_bfloat162& l01,
                                       __nv_bfloat162& l23) {
    h01 = __floats2bfloat162_rn(x.x, x.y);
    h23 = __floats2bfloat162_rn(x.z, x.w);
    l01 = __floats2bfloat162_rn(x.x - __bfloat162float(h01.x),
                                x.y - __bfloat162float(h01.y));
    l23 = __floats2bfloat162_rn(x.z - __bfloat162float(h23.x),
                                x.w - __bfloat162float(h23.y));
}

__global__ __launch_bounds__(256) void split_all_kernel(
    const float* __restrict__ hs, const float* __restrict__ Wq,
    const float* __restrict__ Wk, const float* __restrict__ Wv,
    const float* __restrict__ Wo) {
    const int r = blockIdx.x, c = threadIdx.x * 4;
    const float* src;
    __nv_bfloat16* dst;
    bool alay;
    if (r < 1024) {
        src = hs + (size_t)r * 1024; dst = g_hs2 + (size_t)r * KSPLIT; alay = true;
    } else if (r < 2560) {
        int rr = r - 1024;
        const float* w; int wr;
        if (rr < 256)      { w = Wq; wr = rr; }
        else if (rr < 512) { w = Wk; wr = rr - 256; }
        else               { w = Wv; wr = rr - 512; }
        src = w + (size_t)wr * 1024; dst = g_w1 + (size_t)rr * KSPLIT; alay = false;
    } else {
        int rr = r - 2560;
        src = Wo + (size_t)rr * 1024; dst = g_wo2 + (size_t)rr * KSPLIT; alay = false;
    }
    float4 x = *(const float4*)&src[c];
    __nv_bfloat162 h01, h23, l01, l23;
    split4(x, h01, h23, l01, l23);
    __nv_bfloat162* d0 = (__nv_bfloat162*)&dst[c];
    __nv_bfloat162* d1 = (__nv_bfloat162*)&dst[1024 + c];
    __nv_bfloat162* d2 = (__nv_bfloat162*)&dst[2048 + c];
    d0[0] = h01; d0[1] = h23;
    if (alay) { d1[0] = h01; d1[1] = h23; d2[0] = l01; d2[1] = l23; }
    else      { d1[0] = l01; d1[1] = l23; d2[0] = h01; d2[1] = h23; }
}

// ---------------- mma.sync bf16 NT GEMM, 512 threads (16 warps, 4x4) --------
template <int NTILE>
__global__ __launch_bounds__(512) void mma_gemm_kernel(
    const __nv_bfloat16* __restrict__ A, const __nv_bfloat16* __restrict__ B,
    float* __restrict__ C, int ldc) {
    constexpr int WN   = NTILE / 4;      // warp n-width (32 or 16)
    constexpr int NT8  = WN / 8;         // 8-col mma tiles per warp (4 or 2)
    constexpr int ROWS = 128 + NTILE;
    constexpr int SBYTES = ROWS * ROWB;

    extern __shared__ __align__(128) char sm[];
    const uint32_t sbase = smem_u32(sm);
    const int tid = threadIdx.x, lid = tid & 31, wid = tid >> 5;
    const int m0 = blockIdx.y * 128, n0 = blockIdx.x * NTILE;
    const int wm = wid & 3, wn = wid >> 2;     // 4(m) x 4(n) warp grid

    auto load_stage = [&](int s, int buf) {
        const uint32_t base = sbase + buf * SBYTES;
#pragma unroll
        for (int i = 0; i < ROWS / 64; i++) {
            int idx = tid + i * 512;
            int row = idx >> 3, ch = idx & 7;
            const __nv_bfloat16* g =
                (row < 128)
                    ? A + (size_t)(m0 + row) * KSPLIT + s * 64 + ch * 8
                    : B + (size_t)(n0 + row - 128) * KSPLIT + s * 64 + ch * 8;
            cp16(base + row * ROWB + ch * 16, g);
        }
    };

    auto load_frags = [&](int buf, int k, uint32_t af[2][4],
                          uint32_t bfr[NT8][2]) {
        const uint32_t abase = sbase + buf * SBYTES +
            (wm * 32 + (lid & 15)) * ROWB + (lid >> 4) * 16 + k * 32;
#pragma unroll
        for (int mt = 0; mt < 2; mt++)
            ldsm_x4(af[mt][0], af[mt][1], af[mt][2], af[mt][3],
                    abase + mt * 16 * ROWB);
        const uint32_t bbase = sbase + buf * SBYTES + 128 * ROWB +
            (wn * WN + (lid & 15)) * ROWB + (lid >> 4) * 16 + k * 32;
#pragma unroll
        for (int nt2 = 0; nt2 < NT8 / 2; nt2++) {
            uint32_t r0, r1, r2, r3;
            ldsm_x4(r0, r1, r2, r3, bbase + nt2 * 16 * ROWB);
            bfr[2 * nt2][0] = r0; bfr[2 * nt2][1] = r2;
            bfr[2 * nt2 + 1][0] = r1; bfr[2 * nt2 + 1][1] = r3;
        }
    };

    float acc[2][NT8][4] = {};

    load_stage(0, 0); asm volatile("cp.async.commit_group;" ::: "memory");
    load_stage(1, 1); asm volatile("cp.async.commit_group;" ::: "memory");
    load_stage(2, 2); asm volatile("cp.async.commit_group;" ::: "memory");

    uint32_t af[2][2][4], bfr[2][NT8][2];

    for (int s = 0; s < NSTAGE; s++) {
        const int buf = s & 3;
        asm volatile("cp.async.wait_group 2;" ::: "memory");
        __syncthreads();
        load_frags(buf, 0, af[0], bfr[0]);
        if (s + 3 < NSTAGE) load_stage(s + 3, (s + 3) & 3);
        asm volatile("cp.async.commit_group;" ::: "memory");
#pragma unroll
        for (int k = 0; k < 4; k++) {
            if (k < 3) load_frags(buf, k + 1, af[(k + 1) & 1], bfr[(k + 1) & 1]);
#pragma unroll
            for (int mt = 0; mt < 2; mt++)
#pragma unroll
                for (int nt = 0; nt < NT8; nt++)
                    mma16816(acc[mt][nt], af[k & 1][mt], bfr[k & 1][nt]);
        }
    }

    const int r = lid >> 2, cq = (lid & 3) * 2;
#pragma unroll
    for (int mt = 0; mt < 2; mt++) {
        const int mrow = m0 + wm * 32 + mt * 16 + r;
#pragma unroll
        for (int nt = 0; nt < NT8; nt++) {
            const int col = n0 + wn * WN + nt * 8 + cq;
            *(float2*)&C[(size_t)mrow * ldc + col] =
                make_float2(acc[mt][nt][0], acc[mt][nt][1]);
            *(float2*)&C[(size_t)(mrow + 8) * ldc + col] =
                make_float2(acc[mt][nt][2], acc[mt][nt][3]);
        }
    }
}

// ---------------- FA: polynomial flash attention ----------------------------
__global__ __launch_bounds__(256) void flash_kernel() {
    extern __shared__ __align__(128) char sm[];
    const uint32_t sb = smem_u32(sm);
    float* denS = (float*)(sm + DEN_OFF);       // [4][128]

    const int tb = blockIdx.x, h = blockIdx.y;
    const int tid = threadIdx.x, lid = tid & 31, wid = tid >> 5;
    const int wm = wid & 1, wn = wid >> 1;
    const int r = lid >> 2, cq = (lid & 3) * 2;

    for (int i = tid; i < 512; i += 256) denS[i] = 0.f;

    // build Aq: q split [hi|hi|lo], K=48
    for (int i = tid; i < 2048; i += 256) {
        int t = i >> 4, ii = i & 15;
        float q = g_qkv[(tb * 128 + t) * 1536 + h * 16 + ii];
        __nv_bfloat16 hq = __float2bfloat16(q);
        __nv_bfloat16 lq = __float2bfloat16(q - __bfloat162float(hq));
        __nv_bfloat16* row = (__nv_bfloat16*)(sm + AQ_OFF + t * APITCH);
        row[ii] = hq; row[16 + ii] = hq; row[32 + ii] = lq;
    }

    float acc_o[4][2][4] = {};

    for (int sblk = 0; sblk <= tb; sblk++) {
        __syncthreads();   // previous iteration's smem reads done

        // build Bk: k split [hi|lo|hi]
        for (int i = tid; i < 2048; i += 256) {
            int s = i >> 4, ii = i & 15;
            float k = g_qkv[(sblk * 128 + s) * 1536 + 256 + h * 16 + ii];
            __nv_bfloat16 hk = __float2bfloat16(k);
            __nv_bfloat16 lk = __float2bfloat16(k - __bfloat162float(hk));
            __nv_bfloat16* row = (__nv_bfloat16*)(sm + BK_OFF + s * APITCH);
            row[ii] = hk; row[16 + ii] = lk; row[32 + ii] = hk;
        }
        // build Vh/Vl transposed: [j][s]
        for (int i = tid; i < 8192; i += 256) {
            int s = i >> 6, j = i & 63;
            float v = g_qkv[(sblk * 128 + s) * 1536 + 512 + h * 64 + j];
            __nv_bfloat16 hv = __float2bfloat16(v);
            __nv_bfloat16 lv = __float2bfloat16(v - __bfloat162float(hv));
            ((__nv_bfloat16*)(sm + VH_OFF + j * SPITCH))[s] = hv;
            ((__nv_bfloat16*)(sm + VL_OFF + j * SPITCH))[s] = lv;
        }
        __syncthreads();

        // QK^T: 128x128, K=48 split
        float acc_s[4][4][4] = {};
#pragma unroll
        for (int k = 0; k < 3; k++) {
            uint32_t af[4][4], bf[4][2];
            const uint32_t abase = sb + AQ_OFF +
                (wm * 64 + (lid & 15)) * APITCH + (lid >> 4) * 16 + k * 32;
#pragma unroll
            for (int mt = 0; mt < 4; mt++)
                ldsm_x4(af[mt][0], af[mt][1], af[mt][2], af[mt][3],
                        abase + mt * 16 * APITCH);
            const uint32_t bbase = sb + BK_OFF +
                (wn * 32 + (lid & 15)) * APITCH + (lid >> 4) * 16 + k * 32;
#pragma unroll
            for (int nt2 = 0; nt2 < 2; nt2++) {
                uint32_t r0, r1, r2, r3;
                ldsm_x4(r0, r1, r2, r3, bbase + nt2 * 16 * APITCH);
                bf[2 * nt2][0] = r0; bf[2 * nt2][1] = r2;
                bf[2 * nt2 + 1][0] = r1; bf[2 * nt2 + 1][1] = r3;
            }
#pragma unroll
            for (int mt = 0; mt < 4; mt++)
#pragma unroll
                for (int nt = 0; nt < 4; nt++)
                    mma16816(acc_s[mt][nt], af[mt], bf[nt]);
        }

        // polynomial + mask + den rowsum + split store
        const bool diag = (sblk == tb);
#pragma unroll
        for (int mt = 0; mt < 4; mt++) {
            const int tr0 = wm * 64 + mt * 16 + r;
            const int tr8 = tr0 + 8;
            float d0 = 0.f, d8 = 0.f;
#pragma unroll
            for (int nt = 0; nt < 4; nt++) {
                const int cl = wn * 32 + nt * 8 + cq;
                float* c = acc_s[mt][nt];
                float sc[4];
#pragma unroll
                for (int e = 0; e < 4; e++) {
                    float sd = c[e] * 0.25f;
                    sc[e] = fmaf(0.5f * sd, sd, 1.0f + sd);
                }
                if (diag) {
                    if (cl > tr0) sc[0] = 0.f;
                    if (cl + 1 > tr0) sc[1] = 0.f;
                    if (cl > tr8) sc[2] = 0.f;
                    if (cl + 1 > tr8) sc[3] = 0.f;
                }
                d0 += sc[0] + sc[1];
                d8 += sc[2] + sc[3];
                __nv_bfloat162 h0 = __floats2bfloat162_rn(sc[0], sc[1]);
                __nv_bfloat162 l0 = __floats2bfloat162_rn(
                    sc[0] - __bfloat162float(h0.x), sc[1] - __bfloat162float(h0.y));
                __nv_bfloat162 h8 = __floats2bfloat162_rn(sc[2], sc[3]);
                __nv_bfloat162 l8 = __floats2bfloat162_rn(
                    sc[2] - __bfloat162float(h8.x), sc[3] - __bfloat162float(h8.y));
                *(__nv_bfloat162*)(sm + SH_OFF + tr0 * SPITCH + cl * 2) = h0;
                *(__nv_bfloat162*)(sm + SL_OFF + tr0 * SPITCH + cl * 2) = l0;
                *(__nv_bfloat162*)(sm + SH_OFF + tr8 * SPITCH + cl * 2) = h8;
                *(__nv_bfloat162*)(sm + SL_OFF + tr8 * SPITCH + cl * 2) = l8;
            }
            // reduce within lane-quad (same row)
            d0 += __shfl_xor_sync(0xFFFFFFFF, d0, 1);
            d0 += __shfl_xor_sync(0xFFFFFFFF, d0, 2);
            d8 += __shfl_xor_sync(0xFFFFFFFF, d8, 1);
            d8 += __shfl_xor_sync(0xFFFFFFFF, d8, 2);
            if ((lid & 3) == 0) {
                denS[wn * 128 + tr0] += d0;
                denS[wn * 128 + tr8] += d8;
            }
        }
        __syncthreads();

        // O += Sh@Vh^T + Sh@Vl^T + Sl@Vh^T  (each K=128)
#pragma unroll
        for (int p = 0; p < 3; p++) {
            const uint32_t Ab = sb + (p == 2 ? SL_OFF : SH_OFF);
            const uint32_t Bb = sb + (p == 1 ? VL_OFF : VH_OFF);
#pragma unroll
            for (int k8 = 0; k8 < 8; k8++) {
                uint32_t af[4][4], bf[2][2];
                const uint32_t abase = Ab +
                    (wm * 64 + (lid & 15)) * SPITCH + (lid >> 4) * 16 + k8 * 32;
#pragma unroll
                for (int mt = 0; mt < 4; mt++)
                    ldsm_x4(af[mt][0], af[mt][1], af[mt][2], af[mt][3],
                            abase + mt * 16 * SPITCH);
                const uint32_t bbase = Bb +
                    (wn * 16 + (lid & 15)) * SPITCH + (lid >> 4) * 16 + k8 * 32;
                uint32_t r0, r1, r2, r3;
                ldsm_x4(r0, r1, r2, r3, bbase);
                bf[0][0] = r0; bf[0][1] = r2;
                bf[1][0] = r1; bf[1][1] = r3;
#pragma unroll
                for (int mt = 0; mt < 4; mt++)
#pragma unroll
                    for (int nt = 0; nt < 2; nt++)
                        mma16816(acc_o[mt][nt], af[mt], bf[nt]);
            }
        }
    }
    __syncthreads();

    // epilogue: y = O/den, write split-bf16 y2 ([hi|hi|lo])
#pragma unroll
    for (int mt = 0; mt < 4; mt++) {
        const int row0 = wm * 64 + mt * 16 + r;
        const int row8 = row0 + 8;
        const float den0 = denS[row0] + denS[128 + row0] +
                           denS[256 + row0] + denS[384 + row0] + EPSV;
        const float den8 = denS[row8] + denS[128 + row8] +
                           denS[256 + row8] + denS[384 + row8] + EPSV;
        const float rd0 = 1.0f / den0, rd8 = 1.0f / den8;
#pragma unroll
        for (int nt = 0; nt < 2; nt++) {
            const int col = wn * 16 + nt * 8 + cq;
            float y0 = acc_o[mt][nt][0] * rd0, y1 = acc_o[mt][nt][1] * rd0;
            float y2v = acc_o[mt][nt][2] * rd8, y3 = acc_o[mt][nt][3] * rd8;

            __nv_bfloat162 h0 = __floats2bfloat162_rn(y0, y1);
            __nv_bfloat162 l0 = __floats2bfloat162_rn(
                y0 - __bfloat162float(h0.x), y1 - __bfloat162float(h0.y));
            __nv_bfloat162 h8 = __floats2bfloat162_rn(y2v, y3);
            __nv_bfloat162 l8 = __floats2bfloat162_rn(
                y2v - __bfloat162float(h8.x), y3 - __bfloat162float(h8.y));

            __nv_bfloat16* b0 =
                g_y2 + (size_t)(tb * 128 + row0) * KSPLIT + h * 64 + col;
            *(__nv_bfloat162*)b0 = h0;
            *(__nv_bfloat162*)(b0 + 1024) = h0;
            *(__nv_bfloat162*)(b0 + 2048) = l0;
            __nv_bfloat16* b8 = b0 + (size_t)8 * KSPLIT;
            *(__nv_bfloat162*)b8 = h8;
            *(__nv_bfloat162*)(b8 + 1024) = h8;
            *(__nv_bfloat162*)(b8 + 2048) = l8;
        }
    }
}

// ---------------------------------------------------------------------------
#define SMG1 (4 * (256 * ROWB))       // 147456
#define SMG2 (4 * (192 * ROWB))       // 110592

extern "C" void kernel_launch(void* const* d_in, const int* in_sizes, int n_in,
                              void* d_out, int out_size) {
    (void)in_sizes; (void)n_in; (void)out_size;
    const float* hs = (const float*)d_in[0];
    const float* Wq = (const float*)d_in[1];
    const float* Wk = (const float*)d_in[2];
    const float* Wv = (const float*)d_in[3];
    const float* Wo = (const float*)d_in[4];
    float* out = (float*)d_out;

    cudaFuncSetAttribute((const void*)mma_gemm_kernel<128>,
                         cudaFuncAttributeMaxDynamicSharedMemorySize, SMG1);
    cudaFuncSetAttribute((const void*)mma_gemm_kernel<64>,
                         cudaFuncAttributeMaxDynamicSharedMemorySize, SMG2);
    cudaFuncSetAttribute((const void*)flash_kernel,
                         cudaFuncAttributeMaxDynamicSharedMemorySize, FA_SMEM);

    __nv_bfloat16 *hs2, *w1, *y2, *wo2;
    float* qkv;
    cudaGetSymbolAddress((void**)&hs2, g_hs2);
    cudaGetSymbolAddress((void**)&w1,  g_w1);
    cudaGetSymbolAddress((void**)&y2,  g_y2);
    cudaGetSymbolAddress((void**)&wo2, g_wo2);
    cudaGetSymbolAddress((void**)&qkv, g_qkv);

    split_all_kernel<<<3584, 256>>>(hs, Wq, Wk, Wv, Wo);
    mma_gemm_kernel<128><<<dim3(12, 8), 512, SMG1>>>(hs2, w1, qkv, 1536);
    flash_kernel<<<dim3(8, NH), 256, FA_SMEM>>>();
    mma_gemm_kernel<64><<<dim3(16, 8), 512, SMG2>>>(y2, wo2, out, 1024);
}

// round 15
// speedup vs baseline: 1.0674x; 1.0674x over previous
#include <cuda_runtime.h>
#include <cuda_bf16.h>
#include <cstdint>

// ---------------------------------------------------------------------------
// LinearAttention via polynomial flash attention.
//   phi(q).phi(k) = 1 + s + s^2/2,  s = q.k/4   (Taylor feature identity)
// so causal linear attention == causal polynomial attention:
//   y_t = sum_{s<=t} sc(t,s) v_s / sum_{s<=t} sc(t,s)
//
//   S:  split hs/W1/Wo to K-concat split-bf16 (K=3072)
//   G1: qkv = hs2 @ W1^T   (mma.sync bf16, 4-stage cp.async; round-9 config)
//   FA: per (qb, h), 64-row Q tiles (256 CTAs, 2/SM): loop s-blocks:
//       QK^T HMMA (split K=48), poly+mask+fp32 rowsum,
//       score@V HMMA (3 passes K=128), divide, write split-bf16 y2
//   G2: out = y2 @ Wo2^T
// ---------------------------------------------------------------------------

#define LSEQ   1024
#define NH     16
#define EPSV   1e-12f
#define KSPLIT 3072
#define NSTAGE 48
#define ROWB   144

// flash smem layout (64-row Q tile)
#define APITCH 112                       // 48 bf16 cols + pad
#define SPITCH 272                       // 128 bf16 cols + pad
#define AQ_OFF 0                         // 64  x 112  = 7168
#define BK_OFF 7168                      // 128 x 112  = 14336
#define SH_OFF 21504                     // 64  x 272  = 17408
#define SL_OFF 38912                     // 64  x 272
#define VH_OFF 56320                     // 64  x 272
#define VL_OFF 73728                     // 64  x 272
#define DEN_OFF 91136                    // 4 x 64 floats
#define FA_SMEM 92160

// Scratch (static device globals; no allocation allowed)
__device__ __align__(16) float g_qkv[LSEQ * 1536];
__device__ __align__(16) __nv_bfloat16 g_hs2[LSEQ * KSPLIT];
__device__ __align__(16) __nv_bfloat16 g_w1 [1536 * KSPLIT];
__device__ __align__(16) __nv_bfloat16 g_y2 [LSEQ * KSPLIT];
__device__ __align__(16) __nv_bfloat16 g_wo2[1024 * KSPLIT];

// ---------------- PTX helpers -----------------------------------------------
__device__ __forceinline__ uint32_t smem_u32(const void* p) {
    uint32_t a;
    asm("{ .reg .u64 t; cvta.to.shared.u64 t, %1; cvt.u32.u64 %0, t; }"
        : "=r"(a) : "l"(p));
    return a;
}
__device__ __forceinline__ void cp16(uint32_t saddr, const void* g) {
    asm volatile("cp.async.cg.shared.global [%0], [%1], 16;"
                 :: "r"(saddr), "l"(g) : "memory");
}
__device__ __forceinline__ void ldsm_x4(uint32_t& r0, uint32_t& r1,
                                        uint32_t& r2, uint32_t& r3,
                                        uint32_t addr) {
    asm volatile("ldmatrix.sync.aligned.m8n8.x4.shared.b16 {%0,%1,%2,%3}, [%4];"
                 : "=r"(r0), "=r"(r1), "=r"(r2), "=r"(r3) : "r"(addr));
}
__device__ __forceinline__ void mma16816(float* c, const uint32_t* a,
                                         const uint32_t* b) {
    asm volatile("mma.sync.aligned.m16n8k16.row.col.f32.bf16.bf16.f32 "
                 "{%0,%1,%2,%3}, {%4,%5,%6,%7}, {%8,%9}, {%0,%1,%2,%3};"
                 : "+f"(c[0]), "+f"(c[1]), "+f"(c[2]), "+f"(c[3])
                 : "r"(a[0]), "r"(a[1]), "r"(a[2]), "r"(a[3]),
                   "r"(b[0]), "r"(b[1]));
}

// ---------------- fused split kernel ----------------------------------------
__device__ __forceinline__ void split4(float4 x, __nv_bfloat162& h01,
                                       __nv_bfloat162& h23, __nv_bfloat162& l01,
                                       __nv_bfloat162& l23) {
    h01 = __floats2bfloat162_rn(x.x, x.y);
    h23 = __floats2bfloat162_rn(x.z, x.w);
    l01 = __floats2bfloat162_rn(x.x - __bfloat162float(h01.x),
                                x.y - __bfloat162float(h01.y));
    l23 = __floats2bfloat162_rn(x.z - __bfloat162float(h23.x),
                                x.w - __bfloat162float(h23.y));
}

__global__ __launch_bounds__(256) void split_all_kernel(
    const float* __restrict__ hs, const float* __restrict__ Wq,
    const float* __restrict__ Wk, const float* __restrict__ Wv,
    const float* __restrict__ Wo) {
    const int r = blockIdx.x, c = threadIdx.x * 4;
    const float* src;
    __nv_bfloat16* dst;
    bool alay;
    if (r < 1024) {
        src = hs + (size_t)r * 1024; dst = g_hs2 + (size_t)r * KSPLIT; alay = true;
    } else if (r < 2560) {
        int rr = r - 1024;
        const float* w; int wr;
        if (rr < 256)      { w = Wq; wr = rr; }
        else if (rr < 512) { w = Wk; wr = rr - 256; }
        else               { w = Wv; wr = rr - 512; }
        src = w + (size_t)wr * 1024; dst = g_w1 + (size_t)rr * KSPLIT; alay = false;
    } else {
        int rr = r - 2560;
        src = Wo + (size_t)rr * 1024; dst = g_wo2 + (size_t)rr * KSPLIT; alay = false;
    }
    float4 x = *(const float4*)&src[c];
    __nv_bfloat162 h01, h23, l01, l23;
    split4(x, h01, h23, l01, l23);
    __nv_bfloat162* d0 = (__nv_bfloat162*)&dst[c];
    __nv_bfloat162* d1 = (__nv_bfloat162*)&dst[1024 + c];
    __nv_bfloat162* d2 = (__nv_bfloat162*)&dst[2048 + c];
    d0[0] = h01; d0[1] = h23;
    if (alay) { d1[0] = h01; d1[1] = h23; d2[0] = l01; d2[1] = l23; }
    else      { d1[0] = l01; d1[1] = l23; d2[0] = h01; d2[1] = h23; }
}

// ---------------- mma.sync bf16 NT GEMM (round-9 proven config) -------------
template <int NTILE>
__global__ __launch_bounds__(256) void mma_gemm_kernel(
    const __nv_bfloat16* __restrict__ A, const __nv_bfloat16* __restrict__ B,
    float* __restrict__ C, int ldc) {
    constexpr int WN   = NTILE / 4;
    constexpr int NT8  = WN / 8;
    constexpr int ROWS = 128 + NTILE;
    constexpr int SBYTES = ROWS * ROWB;

    extern __shared__ __align__(128) char sm[];
    const uint32_t sbase = smem_u32(sm);
    const int tid = threadIdx.x, lid = tid & 31, wid = tid >> 5;
    const int m0 = blockIdx.y * 128, n0 = blockIdx.x * NTILE;
    const int wm = wid & 1, wn = wid >> 1;

    auto load_stage = [&](int s, int buf) {
        const uint32_t base = sbase + buf * SBYTES;
#pragma unroll
        for (int i = 0; i < ROWS / 32; i++) {
            int idx = tid + i * 256;
            int row = idx >> 3, ch = idx & 7;
            const __nv_bfloat16* g =
                (row < 128)
                    ? A + (size_t)(m0 + row) * KSPLIT + s * 64 + ch * 8
                    : B + (size_t)(n0 + row - 128) * KSPLIT + s * 64 + ch * 8;
            cp16(base + row * ROWB + ch * 16, g);
        }
    };

    auto load_frags = [&](int buf, int k, uint32_t af[4][4],
                          uint32_t bfr[NT8][2]) {
        const uint32_t abase = sbase + buf * SBYTES +
            (wm * 64 + (lid & 15)) * ROWB + (lid >> 4) * 16 + k * 32;
#pragma unroll
        for (int mt = 0; mt < 4; mt++)
            ldsm_x4(af[mt][0], af[mt][1], af[mt][2], af[mt][3],
                    abase + mt * 16 * ROWB);
        const uint32_t bbase = sbase + buf * SBYTES + 128 * ROWB +
            (wn * WN + (lid & 15)) * ROWB + (lid >> 4) * 16 + k * 32;
#pragma unroll
        for (int nt2 = 0; nt2 < NT8 / 2; nt2++) {
            uint32_t r0, r1, r2, r3;
            ldsm_x4(r0, r1, r2, r3, bbase + nt2 * 16 * ROWB);
            bfr[2 * nt2][0] = r0; bfr[2 * nt2][1] = r2;
            bfr[2 * nt2 + 1][0] = r1; bfr[2 * nt2 + 1][1] = r3;
        }
    };

    float acc[4][NT8][4] = {};

    load_stage(0, 0); asm volatile("cp.async.commit_group;" ::: "memory");
    load_stage(1, 1); asm volatile("cp.async.commit_group;" ::: "memory");
    load_stage(2, 2); asm volatile("cp.async.commit_group;" ::: "memory");

    uint32_t af[2][4][4], bfr[2][NT8][2];

    for (int s = 0; s < NSTAGE; s++) {
        const int buf = s & 3;
        asm volatile("cp.async.wait_group 2;" ::: "memory");
        __syncthreads();
        load_frags(buf, 0, af[0], bfr[0]);
        if (s + 3 < NSTAGE) load_stage(s + 3, (s + 3) & 3);
        asm volatile("cp.async.commit_group;" ::: "memory");
#pragma unroll
        for (int k = 0; k < 4; k++) {
            if (k < 3) load_frags(buf, k + 1, af[(k + 1) & 1], bfr[(k + 1) & 1]);
#pragma unroll
            for (int mt = 0; mt < 4; mt++)
#pragma unroll
                for (int nt = 0; nt < NT8; nt++)
                    mma16816(acc[mt][nt], af[k & 1][mt], bfr[k & 1][nt]);
        }
    }

    const int r = lid >> 2, cq = (lid & 3) * 2;
#pragma unroll
    for (int mt = 0; mt < 4; mt++) {
        const int mrow = m0 + wm * 64 + mt * 16 + r;
#pragma unroll
        for (int nt = 0; nt < NT8; nt++) {
            const int col = n0 + wn * WN + nt * 8 + cq;
            *(float2*)&C[(size_t)mrow * ldc + col] =
                make_float2(acc[mt][nt][0], acc[mt][nt][1]);
            *(float2*)&C[(size_t)(mrow + 8) * ldc + col] =
                make_float2(acc[mt][nt][2], acc[mt][nt][3]);
        }
    }
}

// ---------------- FA: polynomial flash attention, 64-row Q tiles ------------
__global__ __launch_bounds__(256, 2) void flash_kernel() {
    extern __shared__ __align__(128) char sm[];
    const uint32_t sb = smem_u32(sm);
    float* denS = (float*)(sm + DEN_OFF);       // [4][64]

    const int qb = blockIdx.x, h = blockIdx.y;
    const int tid = threadIdx.x, lid = tid & 31, wid = tid >> 5;
    const int wm = wid & 1, wn = wid >> 1;
    const int r = lid >> 2, cq = (lid & 3) * 2;
    const int nsb = (qb >> 1) + 1;              // s-blocks to process
    const int doff = (qb & 1) * 64;             // diag threshold offset

    for (int i = tid; i < 256; i += 256) denS[i] = 0.f;

    // build Aq: q split [hi|hi|lo], K=48  (64 rows)
    for (int i = tid; i < 1024; i += 256) {
        int t = i >> 4, ii = i & 15;
        float q = g_qkv[(qb * 64 + t) * 1536 + h * 16 + ii];
        __nv_bfloat16 hq = __float2bfloat16(q);
        __nv_bfloat16 lq = __float2bfloat16(q - __bfloat162float(hq));
        __nv_bfloat16* row = (__nv_bfloat16*)(sm + AQ_OFF + t * APITCH);
        row[ii] = hq; row[16 + ii] = hq; row[32 + ii] = lq;
    }

    float acc_o[2][2][4] = {};

    for (int sblk = 0; sblk < nsb; sblk++) {
        __syncthreads();   // previous iteration's smem reads done

        // build Bk: k split [hi|lo|hi]   (128 rows)
        for (int i = tid; i < 2048; i += 256) {
            int s = i >> 4, ii = i & 15;
            float k = g_qkv[(sblk * 128 + s) * 1536 + 256 + h * 16 + ii];
            __nv_bfloat16 hk = __float2bfloat16(k);
            __nv_bfloat16 lk = __float2bfloat16(k - __bfloat162float(hk));
            __nv_bfloat16* row = (__nv_bfloat16*)(sm + BK_OFF + s * APITCH);
            row[ii] = hk; row[16 + ii] = lk; row[32 + ii] = hk;
        }
        // build Vh/Vl transposed: [j][s]
        for (int i = tid; i < 8192; i += 256) {
            int s = i >> 6, j = i & 63;
            float v = g_qkv[(sblk * 128 + s) * 1536 + 512 + h * 64 + j];
            __nv_bfloat16 hv = __float2bfloat16(v);
            __nv_bfloat16 lv = __float2bfloat16(v - __bfloat162float(hv));
            ((__nv_bfloat16*)(sm + VH_OFF + j * SPITCH))[s] = hv;
            ((__nv_bfloat16*)(sm + VL_OFF + j * SPITCH))[s] = lv;
        }
        __syncthreads();

        // QK^T: 64x128, K=48 split   (warp tile 32m x 32n)
        float acc_s[2][4][4] = {};
#pragma unroll
        for (int k = 0; k < 3; k++) {
            uint32_t af[2][4], bf[4][2];
            const uint32_t abase = sb + AQ_OFF +
                (wm * 32 + (lid & 15)) * APITCH + (lid >> 4) * 16 + k * 32;
#pragma unroll
            for (int mt = 0; mt < 2; mt++)
                ldsm_x4(af[mt][0], af[mt][1], af[mt][2], af[mt][3],
                        abase + mt * 16 * APITCH);
            const uint32_t bbase = sb + BK_OFF +
                (wn * 32 + (lid & 15)) * APITCH + (lid >> 4) * 16 + k * 32;
#pragma unroll
            for (int nt2 = 0; nt2 < 2; nt2++) {
                uint32_t r0, r1, r2, r3;
                ldsm_x4(r0, r1, r2, r3, bbase + nt2 * 16 * APITCH);
                bf[2 * nt2][0] = r0; bf[2 * nt2][1] = r2;
                bf[2 * nt2 + 1][0] = r1; bf[2 * nt2 + 1][1] = r3;
            }
#pragma unroll
            for (int mt = 0; mt < 2; mt++)
#pragma unroll
                for (int nt = 0; nt < 4; nt++)
                    mma16816(acc_s[mt][nt], af[mt], bf[nt]);
        }

        // polynomial + mask + den rowsum + split store
        const bool diag = (sblk == (qb >> 1));
#pragma unroll
        for (int mt = 0; mt < 2; mt++) {
            const int tr0 = wm * 32 + mt * 16 + r;     // local q row 0..63
            const int tr8 = tr0 + 8;
            const int th0 = tr0 + doff, th8 = tr8 + doff;  // mask thresholds
            float d0 = 0.f, d8 = 0.f;
#pragma unroll
            for (int nt = 0; nt < 4; nt++) {
                const int cl = wn * 32 + nt * 8 + cq;
                float* c = acc_s[mt][nt];
                float sc[4];
#pragma unroll
                for (int e = 0; e < 4; e++) {
                    float sd = c[e] * 0.25f;
                    sc[e] = fmaf(0.5f * sd, sd, 1.0f + sd);
                }
                if (diag) {
                    if (cl > th0) sc[0] = 0.f;
                    if (cl + 1 > th0) sc[1] = 0.f;
                    if (cl > th8) sc[2] = 0.f;
                    if (cl + 1 > th8) sc[3] = 0.f;
                }
                d0 += sc[0] + sc[1];
                d8 += sc[2] + sc[3];
                __nv_bfloat162 h0 = __floats2bfloat162_rn(sc[0], sc[1]);
                __nv_bfloat162 l0 = __floats2bfloat162_rn(
                    sc[0] - __bfloat162float(h0.x), sc[1] - __bfloat162float(h0.y));
                __nv_bfloat162 h8 = __floats2bfloat162_rn(sc[2], sc[3]);
                __nv_bfloat162 l8 = __floats2bfloat162_rn(
                    sc[2] - __bfloat162float(h8.x), sc[3] - __bfloat162float(h8.y));
                *(__nv_bfloat162*)(sm + SH_OFF + tr0 * SPITCH + cl * 2) = h0;
                *(__nv_bfloat162*)(sm + SL_OFF + tr0 * SPITCH + cl * 2) = l0;
                *(__nv_bfloat162*)(sm + SH_OFF + tr8 * SPITCH + cl * 2) = h8;
                *(__nv_bfloat162*)(sm + SL_OFF + tr8 * SPITCH + cl * 2) = l8;
            }
            // reduce within lane-quad (same row)
            d0 += __shfl_xor_sync(0xFFFFFFFF, d0, 1);
            d0 += __shfl_xor_sync(0xFFFFFFFF, d0, 2);
            d8 += __shfl_xor_sync(0xFFFFFFFF, d8, 1);
            d8 += __shfl_xor_sync(0xFFFFFFFF, d8, 2);
            if ((lid & 3) == 0) {
                denS[wn * 64 + tr0] += d0;
                denS[wn * 64 + tr8] += d8;
            }
        }
        __syncthreads();

        // O += Sh@Vh^T + Sh@Vl^T + Sl@Vh^T  (each K=128, warp tile 32m x 16n)
#pragma unroll
        for (int p = 0; p < 3; p++) {
            const uint32_t Ab = sb + (p == 2 ? SL_OFF : SH_OFF);
            const uint32_t Bb = sb + (p == 1 ? VL_OFF : VH_OFF);
#pragma unroll
            for (int k8 = 0; k8 < 8; k8++) {
                uint32_t af[2][4], bf[2][2];
                const uint32_t abase = Ab +
                    (wm * 32 + (lid & 15)) * SPITCH + (lid >> 4) * 16 + k8 * 32;
#pragma unroll
                for (int mt = 0; mt < 2; mt++)
                    ldsm_x4(af[mt][0], af[mt][1], af[mt][2], af[mt][3],
                            abase + mt * 16 * SPITCH);
                const uint32_t bbase = Bb +
                    (wn * 16 + (lid & 15)) * SPITCH + (lid >> 4) * 16 + k8 * 32;
                uint32_t r0, r1, r2, r3;
                ldsm_x4(r0, r1, r2, r3, bbase);
                bf[0][0] = r0; bf[0][1] = r2;
                bf[1][0] = r1; bf[1][1] = r3;
#pragma unroll
                for (int mt = 0; mt < 2; mt++)
#pragma unroll
                    for (int nt = 0; nt < 2; nt++)
                        mma16816(acc_o[mt][nt], af[mt], bf[nt]);
            }
        }
    }
    __syncthreads();

    // epilogue: y = O/den, write split-bf16 y2 ([hi|hi|lo])
#pragma unroll
    for (int mt = 0; mt < 2; mt++) {
        const int row0 = wm * 32 + mt * 16 + r;
        const int row8 = row0 + 8;
        const float den0 = denS[row0] + denS[64 + row0] +
                           denS[128 + row0] + denS[192 + row0] + EPSV;
        const float den8 = denS[row8] + denS[64 + row8] +
                           denS[128 + row8] + denS[192 + row8] + EPSV;
        const float rd0 = 1.0f / den0, rd8 = 1.0f / den8;
#pragma unroll
        for (int nt = 0; nt < 2; nt++) {
            const int col = wn * 16 + nt * 8 + cq;
            float y0 = acc_o[mt][nt][0] * rd0, y1 = acc_o[mt][nt][1] * rd0;
            float y2v = acc_o[mt][nt][2] * rd8, y3 = acc_o[mt][nt][3] * rd8;

            __nv_bfloat162 h0 = __floats2bfloat162_rn(y0, y1);
            __nv_bfloat162 l0 = __floats2bfloat162_rn(
                y0 - __bfloat162float(h0.x), y1 - __bfloat162float(h0.y));
            __nv_bfloat162 h8 = __floats2bfloat162_rn(y2v, y3);
            __nv_bfloat162 l8 = __floats2bfloat162_rn(
                y2v - __bfloat162float(h8.x), y3 - __bfloat162float(h8.y));

            __nv_bfloat16* b0 =
                g_y2 + (size_t)(qb * 64 + row0) * KSPLIT + h * 64 + col;
            *(__nv_bfloat162*)b0 = h0;
            *(__nv_bfloat162*)(b0 + 1024) = h0;
            *(__nv_bfloat162*)(b0 + 2048) = l0;
            __nv_bfloat16* b8 = b0 + (size_t)8 * KSPLIT;
            *(__nv_bfloat162*)b8 = h8;
            *(__nv_bfloat162*)(b8 + 1024) = h8;
            *(__nv_bfloat162*)(b8 + 2048) = l8;
        }
    }
}

// ---------------------------------------------------------------------------
#define SMG1 (4 * (256 * ROWB))       // 147456
#define SMG2 (4 * (192 * ROWB))       // 110592

extern "C" void kernel_launch(void* const* d_in, const int* in_sizes, int n_in,
                              void* d_out, int out_size) {
    (void)in_sizes; (void)n_in; (void)out_size;
    const float* hs = (const float*)d_in[0];
    const float* Wq = (const float*)d_in[1];
    const float* Wk = (const float*)d_in[2];
    const float* Wv = (const float*)d_in[3];
    const float* Wo = (const float*)d_in[4];
    float* out = (float*)d_out;

    cudaFuncSetAttribute((const void*)mma_gemm_kernel<128>,
                         cudaFuncAttributeMaxDynamicSharedMemorySize, SMG1);
    cudaFuncSetAttribute((const void*)mma_gemm_kernel<64>,
                         cudaFuncAttributeMaxDynamicSharedMemorySize, SMG2);
    cudaFuncSetAttribute((const void*)flash_kernel,
                         cudaFuncAttributeMaxDynamicSharedMemorySize, FA_SMEM);

    __nv_bfloat16 *hs2, *w1, *y2, *wo2;
    float* qkv;
    cudaGetSymbolAddress((void**)&hs2, g_hs2);
    cudaGetSymbolAddress((void**)&w1,  g_w1);
    cudaGetSymbolAddress((void**)&y2,  g_y2);
    cudaGetSymbolAddress((void**)&wo2, g_wo2);
    cudaGetSymbolAddress((void**)&qkv, g_qkv);

    split_all_kernel<<<3584, 256>>>(hs, Wq, Wk, Wv, Wo);
    mma_gemm_kernel<128><<<dim3(12, 8), 256, SMG1>>>(hs2, w1, qkv, 1536);
    flash_kernel<<<dim3(16, NH), 256, FA_SMEM>>>();
    mma_gemm_kernel<64><<<dim3(16, 8), 256, SMG2>>>(y2, wo2, out, 1024);
}